// round 8
// baseline (speedup 1.0000x reference)
#include <cuda_runtime.h>
#include <cstdint>

// DIN attention-seq-pooling, round 8: fp16 mma.sync + LDS.64 fragment pairing.
// vs round 7 (109us): physical column permutation (per 8-half2 group:
// phys = 2(j&3)+(j>>2)) makes every A/B fragment one LDS.64 (conflict-free,
// strides ≡8 mod 32); prep_qw merged into the main prologue (one less launch,
// no g_qW round-trip). smem 53.4KB, 4 CTAs/SM.
//  MMA1: D1[16,80] = k[16,64] @ B1eff[64,80]   (fp16 in, fp32 acc)
//  h1 = sigmoid(D1 + qW) packed to half2 in regs (== MMA2 A-fragments)
//  MMA2: D2[16,40] = h1[16,80] @ W2T[80,40]
//  score = sigmoid(D2+b2)@Wd + bd, mask t<L; pool from GLOBAL fp32 k.

#define TT 200
#define EE 64
#define HH1 80
#define HH2 40
#define KSTR 40      // all strides ≡ 8 mod 32 -> conflict-free LDS.64
#define B1STR 40
#define W2STR 40

typedef unsigned long long ull;

__device__ float  g_W1sum[EE * HH1];       // W1a + W1c, [e*80+n]
__device__ float2 g_W1pair[HH1 * EE];      // {W1b-W1c, W1d}, [n*64+e]
__device__ unsigned g_W2Th[HH2 * W2STR];   // half2 image [n][phys k2]

// phys slot of logical half2-col c2 within its 8-col group
__host__ __device__ __forceinline__ int physcol(int c2) {
    int g = c2 >> 3, j = c2 & 7;
    return (g << 3) | ((j & 3) << 1) | (j >> 2);
}

__device__ __forceinline__ unsigned pack_h2(float lo, float hi) {
    unsigned r;
    asm("cvt.rn.f16x2.f32 %0, %1, %2;" : "=r"(r) : "f"(hi), "f"(lo));
    return r;
}
__device__ __forceinline__ float sigmoid_tanh(float x) {
    float t;
    asm("tanh.approx.f32 %0, %1;" : "=f"(t) : "f"(x * 0.5f));
    return fmaf(t, 0.5f, 0.5f);
}
__device__ __forceinline__ void mma_f16(float* d, unsigned a0, unsigned a1,
                                        unsigned a2, unsigned a3,
                                        unsigned b0, unsigned b1) {
    asm volatile(
        "mma.sync.aligned.m16n8k16.row.col.f32.f16.f16.f32 "
        "{%0,%1,%2,%3}, {%4,%5,%6,%7}, {%8,%9}, {%0,%1,%2,%3};"
        : "+f"(d[0]), "+f"(d[1]), "+f"(d[2]), "+f"(d[3])
        : "r"(a0), "r"(a1), "r"(a2), "r"(a3), "r"(b0), "r"(b1));
}

// ---------------- prep kernel ----------------
__global__ void prep_pack(const float* __restrict__ W1, const float* __restrict__ W2) {
    int i = blockIdx.x * 256 + threadIdx.x;
    if (i < EE * HH1) {                    // i = e*80+n, coalesced W1 reads
        int e = i / HH1, n = i - e * HH1;
        g_W1sum[i] = W1[i] + W1[2 * EE * HH1 + i];
        float2 p;
        p.x = W1[EE * HH1 + i] - W1[2 * EE * HH1 + i];
        p.y = W1[3 * EE * HH1 + i];
        g_W1pair[n * EE + e] = p;
    }
    if (i < HH2 * W2STR) {                 // 40 n x 40 logical half2-cols
        int n = i / W2STR, c2 = i - n * W2STR;
        float v0 = W2[(2 * c2) * HH2 + n];
        float v1 = W2[(2 * c2 + 1) * HH2 + n];
        g_W2Th[n * W2STR + physcol(c2)] = pack_h2(v0, v1);
    }
}

// ---------------- smem layout (32-bit word index) ----------------
#define SM_K    0                         // 208 x 40 = 8320
#define SM_B1   8320                      // 80 x 40 = 3200
#define SM_W2T  11520                     // 40 x 40 = 1600
#define SM_QW   13120                     // 80 f
#define SM_Q    13200                     // 64 f
#define SM_B2V  13264                     // 40 f
#define SM_WD   13304                     // 40 f
#define SM_SSC  13344                     // 208 f
#define SM_PART 13552                     // 128 f
#define SM_WORDS 13680
#define SM_BYTES (SM_WORDS * 4)           // 54720 -> 4 CTAs/SM

__global__ void __launch_bounds__(128, 4)
din_mma_kernel(const float* __restrict__ query,
               const float* __restrict__ keys,
               const void*  __restrict__ klen,
               const float* __restrict__ b1,
               const float* __restrict__ b2,
               const float* __restrict__ Wd,
               const float* __restrict__ bd,
               float* __restrict__ out)
{
    extern __shared__ float smf[];
    unsigned* smu = (unsigned*)smf;
    const int b    = blockIdx.x;
    const int tid  = threadIdx.x;
    const int wid  = tid >> 5;
    const int lane = tid & 31;
    const int gr   = lane >> 2;     // group row 0..7
    const int tg   = lane & 3;      // thread-in-group 0..3

    // ---- length (int64 vs silently-int32 jax) ----
    const long long* L64 = (const long long*)klen;
    const int*       L32 = (const int*)klen;
    bool is64 = ((ull)L64[0] <= 0xFFFFFFFFull) && ((ull)L64[1] <= 0xFFFFFFFFull) &&
                ((ull)L64[2] <= 0xFFFFFFFFull) && ((ull)L64[3] <= 0xFFFFFFFFull);
    int L = is64 ? (int)L64[b] : L32[b];
    if (L < 0) L = 0;
    if (L > TT) L = TT;
    if (L == 0) {
        if (tid < EE) out[b * EE + tid] = 0.0f;
        return;
    }
    const int ntiles = (L + 15) >> 4;
    const float* kb = keys + (size_t)b * TT * EE;

    // ---- stage q / scalars / W2T ----
    if (tid < EE)  smf[SM_Q + tid]  = query[b * EE + tid];
    if (tid < HH2) { smf[SM_B2V + tid] = b2[tid]; smf[SM_WD + tid] = Wd[tid]; }
    {
        const uint2* src = (const uint2*)g_W2Th;
        uint2* dst = (uint2*)&smu[SM_W2T];
        for (int i = tid; i < HH2 * W2STR / 2; i += 128) dst[i] = src[i];
    }

    // ---- stage k rows as half2, permuted cols, coalesced LDG ----
    {
        const int nrows = ntiles * 16;
        for (int i = tid; i < nrows * 16; i += 128) {
            int r = i >> 4, c4 = i & 15;            // logical half2 cols 2c4, 2c4+1
            float4 v = make_float4(0.f, 0.f, 0.f, 0.f);
            if (r < TT) v = *(const float4*)(kb + (size_t)r * EE + c4 * 4);
            smu[SM_K + r * KSTR + physcol(2 * c4)]     = pack_h2(v.x, v.y);
            smu[SM_K + r * KSTR + physcol(2 * c4 + 1)] = pack_h2(v.z, v.w);
        }
    }
    __syncthreads();

    // ---- qW = b1 + q @ W1sum (merged prep_qw) ----
    if (tid < HH1) {
        float acc = b1[tid];
        #pragma unroll 8
        for (int e = 0; e < EE; e++)
            acc += smf[SM_Q + e] * g_W1sum[e * HH1 + tid];
        smf[SM_QW + tid] = acc;
    }

    // ---- B1eff half2 image: [n][phys e2],  bc + q_e * d ----
    for (int i = tid; i < HH1 * (EE / 2); i += 128) {
        int n = i >> 5, e2 = i & 31;
        float4 w = *(const float4*)&g_W1pair[n * EE + 2 * e2];   // {bc0,d0,bc1,d1}
        float q0 = smf[SM_Q + 2 * e2], q1 = smf[SM_Q + 2 * e2 + 1];
        smu[SM_B1 + n * B1STR + physcol(e2)] = pack_h2(fmaf(q0, w.y, w.x),
                                                       fmaf(q1, w.w, w.z));
    }
    __syncthreads();

    const float bdv = bd[0];

    // ---- warp-owned 16-token tiles ----
    for (int mt = wid; mt < ntiles; mt += 4) {
        const int rbase = mt * 16;
        const int r0 = rbase + gr, r1 = r0 + 8;

        // MMA1: D1[16,80] = k @ B1eff  (4 ksteps of 16)
        float d1[10][4];
        #pragma unroll
        for (int nf = 0; nf < 10; nf++)
            d1[nf][0] = d1[nf][1] = d1[nf][2] = d1[nf][3] = 0.0f;

        #pragma unroll
        for (int ks = 0; ks < 4; ks++) {
            uint2 af0 = *(const uint2*)&smu[SM_K + r0 * KSTR + 8 * ks + 2 * tg];
            uint2 af1 = *(const uint2*)&smu[SM_K + r1 * KSTR + 8 * ks + 2 * tg];
            #pragma unroll
            for (int nf = 0; nf < 10; nf++) {
                uint2 bf = *(const uint2*)&smu[SM_B1 + (8 * nf + gr) * B1STR
                                               + 8 * ks + 2 * tg];
                mma_f16(d1[nf], af0.x, af1.x, af0.y, af1.y, bf.x, bf.y);
            }
        }

        // h1 = sigmoid(D1 + qW) packed half2 in regs == MMA2 A-fragments
        unsigned haA[10], haB[10];
        #pragma unroll
        for (int nf = 0; nf < 10; nf++) {
            int j0 = nf * 8 + 2 * tg;
            float qlo = smf[SM_QW + j0], qhi = smf[SM_QW + j0 + 1];
            haA[nf] = pack_h2(sigmoid_tanh(d1[nf][0] + qlo),
                              sigmoid_tanh(d1[nf][1] + qhi));
            haB[nf] = pack_h2(sigmoid_tanh(d1[nf][2] + qlo),
                              sigmoid_tanh(d1[nf][3] + qhi));
        }

        // MMA2: D2[16,40] = h1 @ W2T  (5 ksteps of 16)
        float d2[5][4];
        #pragma unroll
        for (int nf = 0; nf < 5; nf++)
            d2[nf][0] = d2[nf][1] = d2[nf][2] = d2[nf][3] = 0.0f;

        #pragma unroll
        for (int ks = 0; ks < 5; ks++) {
            unsigned a0 = haA[2 * ks];
            unsigned a1 = haB[2 * ks];
            unsigned a2 = haA[2 * ks + 1];
            unsigned a3 = haB[2 * ks + 1];
            #pragma unroll
            for (int nf = 0; nf < 5; nf++) {
                uint2 bf = *(const uint2*)&smu[SM_W2T + (8 * nf + gr) * W2STR
                                               + 8 * ks + 2 * tg];
                mma_f16(d2[nf], a0, a1, a2, a3, bf.x, bf.y);
            }
        }

        // score = bd + sum_j sigmoid(D2+b2)*Wd ; reduce over tg
        float slo = 0.0f, shi = 0.0f;
        #pragma unroll
        for (int nf = 0; nf < 5; nf++) {
            int j0 = nf * 8 + 2 * tg;
            float blo = smf[SM_B2V + j0], bhi = smf[SM_B2V + j0 + 1];
            float wlo = smf[SM_WD + j0],  whi = smf[SM_WD + j0 + 1];
            slo += sigmoid_tanh(d2[nf][0] + blo) * wlo
                 + sigmoid_tanh(d2[nf][1] + bhi) * whi;
            shi += sigmoid_tanh(d2[nf][2] + blo) * wlo
                 + sigmoid_tanh(d2[nf][3] + bhi) * whi;
        }
        slo += __shfl_xor_sync(0xffffffffu, slo, 1);
        slo += __shfl_xor_sync(0xffffffffu, slo, 2);
        shi += __shfl_xor_sync(0xffffffffu, shi, 1);
        shi += __shfl_xor_sync(0xffffffffu, shi, 2);
        if (tg == 0) {
            int t0 = rbase + gr, t1 = rbase + gr + 8;
            if (t0 < L) smf[SM_SSC + t0] = slo + bdv;
            if (t1 < L) smf[SM_SSC + t1] = shi + bdv;
        }
    }
    __syncthreads();

    // ---- pooling from GLOBAL fp32 k (coalesced 256B per t) ----
    {
        int e = tid & 63, half = tid >> 6;
        const float* kp = kb + e;
        float acc = 0.0f;
        #pragma unroll 8
        for (int t = half; t < L; t += 2)
            acc += smf[SM_SSC + t] * kp[(size_t)t * EE];
        smf[SM_PART + tid] = acc;
    }
    __syncthreads();
    if (tid < EE)
        out[b * EE + tid] = smf[SM_PART + tid] + smf[SM_PART + EE + tid];
}

extern "C" void kernel_launch(void* const* d_in, const int* in_sizes, int n_in,
                              void* d_out, int out_size)
{
    const float* query = (const float*)d_in[0];
    const float* keys  = (const float*)d_in[1];
    const void*  klen  = d_in[2];
    const float* W1    = (const float*)d_in[3];
    const float* b1    = (const float*)d_in[4];
    const float* W2    = (const float*)d_in[5];
    const float* b2    = (const float*)d_in[6];
    const float* Wd    = (const float*)d_in[7];
    const float* bd    = (const float*)d_in[8];
    float* out = (float*)d_out;

    const int B = in_sizes[0] / EE;  // 4096

    static int configured = 0;
    if (!configured) {
        cudaFuncSetAttribute(din_mma_kernel,
                             cudaFuncAttributeMaxDynamicSharedMemorySize, SM_BYTES);
        configured = 1;
    }

    prep_pack<<<20, 256>>>(W1, W2);
    din_mma_kernel<<<B, 128, SM_BYTES>>>(query, keys, klen, b1, b2, Wd, bd, out);
}

// round 9
// speedup vs baseline: 1.2383x; 1.2383x over previous
#include <cuda_runtime.h>
#include <cstdint>

// DIN attention-seq-pooling, round 9: persistent CTAs + atomic work queue.
// vs round 8 (114us) / round 7 (109us): grid = 608 persistent CTAs pull batch
// indices from a device counter (reset each launch). Kills wave tails +
// balances variable-L batches; W2T/scalars staged once per CTA.
// Tile math unchanged: fp16 m16n8k16, reg-resident h1, LDS.64 fragments.

#define TT 200
#define EE 64
#define HH1 80
#define HH2 40
#define KSTR 40      // all strides ≡ 8 mod 32 -> conflict-free LDS.64
#define B1STR 40
#define W2STR 40
#define NCTA 608

typedef unsigned long long ull;

__device__ float  g_W1sum[EE * HH1];       // W1a + W1c, [e*80+n]
__device__ float2 g_W1pair[HH1 * EE];      // {W1b-W1c, W1d}, [n*64+e]
__device__ unsigned g_W2Th[HH2 * W2STR];   // half2 image [n][phys k2]
__device__ int    g_ctr;                   // persistent work counter

// phys slot of logical half2-col c2 within its 8-col group
__host__ __device__ __forceinline__ int physcol(int c2) {
    int g = c2 >> 3, j = c2 & 7;
    return (g << 3) | ((j & 3) << 1) | (j >> 2);
}

__device__ __forceinline__ unsigned pack_h2(float lo, float hi) {
    unsigned r;
    asm("cvt.rn.f16x2.f32 %0, %1, %2;" : "=r"(r) : "f"(hi), "f"(lo));
    return r;
}
__device__ __forceinline__ float sigmoid_tanh(float x) {
    float t;
    asm("tanh.approx.f32 %0, %1;" : "=f"(t) : "f"(x * 0.5f));
    return fmaf(t, 0.5f, 0.5f);
}
__device__ __forceinline__ void mma_f16(float* d, unsigned a0, unsigned a1,
                                        unsigned a2, unsigned a3,
                                        unsigned b0, unsigned b1) {
    asm volatile(
        "mma.sync.aligned.m16n8k16.row.col.f32.f16.f16.f32 "
        "{%0,%1,%2,%3}, {%4,%5,%6,%7}, {%8,%9}, {%0,%1,%2,%3};"
        : "+f"(d[0]), "+f"(d[1]), "+f"(d[2]), "+f"(d[3])
        : "r"(a0), "r"(a1), "r"(a2), "r"(a3), "r"(b0), "r"(b1));
}

// ---------------- prep kernels ----------------
__global__ void reset_ctr() { g_ctr = 0; }

__global__ void prep_pack(const float* __restrict__ W1, const float* __restrict__ W2) {
    int i = blockIdx.x * 256 + threadIdx.x;
    if (i < EE * HH1) {                    // i = e*80+n, coalesced W1 reads
        int e = i / HH1, n = i - e * HH1;
        g_W1sum[i] = W1[i] + W1[2 * EE * HH1 + i];
        float2 p;
        p.x = W1[EE * HH1 + i] - W1[2 * EE * HH1 + i];
        p.y = W1[3 * EE * HH1 + i];
        g_W1pair[n * EE + e] = p;
    }
    if (i < HH2 * W2STR) {                 // 40 n x 40 logical half2-cols
        int n = i / W2STR, c2 = i - n * W2STR;
        float v0 = W2[(2 * c2) * HH2 + n];
        float v1 = W2[(2 * c2 + 1) * HH2 + n];
        g_W2Th[n * W2STR + physcol(c2)] = pack_h2(v0, v1);
    }
}

// ---------------- smem layout (32-bit word index) ----------------
#define SM_K    0                         // 208 x 40 = 8320
#define SM_B1   8320                      // 80 x 40 = 3200
#define SM_W2T  11520                     // 40 x 40 = 1600
#define SM_QW   13120                     // 80 f
#define SM_Q    13200                     // 64 f
#define SM_B2V  13264                     // 40 f
#define SM_WD   13304                     // 40 f
#define SM_SSC  13344                     // 208 f
#define SM_PART 13552                     // 128 f
#define SM_BIDX 13680                     // 1 (current batch index)
#define SM_WORDS 13684
#define SM_BYTES (SM_WORDS * 4)           // 54736 -> 4 CTAs/SM

__global__ void __launch_bounds__(128, 4)
din_mma_kernel(const float* __restrict__ query,
               const float* __restrict__ keys,
               const void*  __restrict__ klen,
               const float* __restrict__ b1,
               const float* __restrict__ b2,
               const float* __restrict__ Wd,
               const float* __restrict__ bd,
               float* __restrict__ out,
               int B)
{
    extern __shared__ float smf[];
    unsigned* smu = (unsigned*)smf;
    int* smi = (int*)smf;
    const int tid  = threadIdx.x;
    const int wid  = tid >> 5;
    const int lane = tid & 31;
    const int gr   = lane >> 2;     // group row 0..7
    const int tg   = lane & 3;      // thread-in-group 0..3

    // ---- per-CTA one-time staging: W2T, b2, Wd ----
    if (tid < HH2) { smf[SM_B2V + tid] = b2[tid]; smf[SM_WD + tid] = Wd[tid]; }
    {
        const uint2* src = (const uint2*)g_W2Th;
        uint2* dst = (uint2*)&smu[SM_W2T];
        for (int i = tid; i < HH2 * W2STR / 2; i += 128) dst[i] = src[i];
    }
    const float bdv = bd[0];

    // ---- length dtype detection once (int64 vs silently-int32 jax) ----
    const long long* L64 = (const long long*)klen;
    const int*       L32 = (const int*)klen;
    const bool is64 = ((ull)L64[0] <= 0xFFFFFFFFull) && ((ull)L64[1] <= 0xFFFFFFFFull) &&
                      ((ull)L64[2] <= 0xFFFFFFFFull) && ((ull)L64[3] <= 0xFFFFFFFFull);

    // ---- persistent work loop ----
    while (true) {
        if (tid == 0) smi[SM_BIDX] = atomicAdd(&g_ctr, 1);
        __syncthreads();               // broadcast b; also fences prev batch
        const int b = smi[SM_BIDX];
        if (b >= B) break;

        int L = is64 ? (int)L64[b] : L32[b];
        if (L < 0) L = 0;
        if (L > TT) L = TT;
        if (L == 0) {
            if (tid < EE) out[(size_t)b * EE + tid] = 0.0f;
            continue;                  // uniform; loop-top sync re-converges
        }
        const int ntiles = (L + 15) >> 4;
        const float* kb = keys + (size_t)b * TT * EE;

        // ---- stage q + k rows (half2, permuted cols, coalesced LDG) ----
        if (tid < EE) smf[SM_Q + tid] = query[(size_t)b * EE + tid];
        {
            const int nrows = ntiles * 16;
            for (int i = tid; i < nrows * 16; i += 128) {
                int r = i >> 4, c4 = i & 15;
                float4 v = make_float4(0.f, 0.f, 0.f, 0.f);
                if (r < TT) v = *(const float4*)(kb + (size_t)r * EE + c4 * 4);
                smu[SM_K + r * KSTR + physcol(2 * c4)]     = pack_h2(v.x, v.y);
                smu[SM_K + r * KSTR + physcol(2 * c4 + 1)] = pack_h2(v.z, v.w);
            }
        }
        __syncthreads();

        // ---- qW = b1 + q @ W1sum ----
        if (tid < HH1) {
            float acc = b1[tid];
            #pragma unroll 8
            for (int e = 0; e < EE; e++)
                acc += smf[SM_Q + e] * g_W1sum[e * HH1 + tid];
            smf[SM_QW + tid] = acc;
        }
        // ---- B1eff half2 image: [n][phys e2],  bc + q_e * d ----
        for (int i = tid; i < HH1 * (EE / 2); i += 128) {
            int n = i >> 5, e2 = i & 31;
            float4 w = *(const float4*)&g_W1pair[n * EE + 2 * e2]; // {bc0,d0,bc1,d1}
            float q0 = smf[SM_Q + 2 * e2], q1 = smf[SM_Q + 2 * e2 + 1];
            smu[SM_B1 + n * B1STR + physcol(e2)] = pack_h2(fmaf(q0, w.y, w.x),
                                                           fmaf(q1, w.w, w.z));
        }
        __syncthreads();

        // ---- warp-owned 16-token tiles ----
        for (int mt = wid; mt < ntiles; mt += 4) {
            const int rbase = mt * 16;
            const int r0 = rbase + gr, r1 = r0 + 8;

            // MMA1: D1[16,80] = k @ B1eff  (4 ksteps of 16)
            float d1[10][4];
            #pragma unroll
            for (int nf = 0; nf < 10; nf++)
                d1[nf][0] = d1[nf][1] = d1[nf][2] = d1[nf][3] = 0.0f;

            #pragma unroll
            for (int ks = 0; ks < 4; ks++) {
                uint2 af0 = *(const uint2*)&smu[SM_K + r0 * KSTR + 8 * ks + 2 * tg];
                uint2 af1 = *(const uint2*)&smu[SM_K + r1 * KSTR + 8 * ks + 2 * tg];
                #pragma unroll
                for (int nf = 0; nf < 10; nf++) {
                    uint2 bf = *(const uint2*)&smu[SM_B1 + (8 * nf + gr) * B1STR
                                                   + 8 * ks + 2 * tg];
                    mma_f16(d1[nf], af0.x, af1.x, af0.y, af1.y, bf.x, bf.y);
                }
            }

            // h1 = sigmoid(D1 + qW) packed half2 in regs == MMA2 A-fragments
            unsigned haA[10], haB[10];
            #pragma unroll
            for (int nf = 0; nf < 10; nf++) {
                int j0 = nf * 8 + 2 * tg;
                float qlo = smf[SM_QW + j0], qhi = smf[SM_QW + j0 + 1];
                haA[nf] = pack_h2(sigmoid_tanh(d1[nf][0] + qlo),
                                  sigmoid_tanh(d1[nf][1] + qhi));
                haB[nf] = pack_h2(sigmoid_tanh(d1[nf][2] + qlo),
                                  sigmoid_tanh(d1[nf][3] + qhi));
            }

            // MMA2: D2[16,40] = h1 @ W2T  (5 ksteps of 16)
            float d2[5][4];
            #pragma unroll
            for (int nf = 0; nf < 5; nf++)
                d2[nf][0] = d2[nf][1] = d2[nf][2] = d2[nf][3] = 0.0f;

            #pragma unroll
            for (int ks = 0; ks < 5; ks++) {
                unsigned a0 = haA[2 * ks];
                unsigned a1 = haB[2 * ks];
                unsigned a2 = haA[2 * ks + 1];
                unsigned a3 = haB[2 * ks + 1];
                #pragma unroll
                for (int nf = 0; nf < 5; nf++) {
                    uint2 bf = *(const uint2*)&smu[SM_W2T + (8 * nf + gr) * W2STR
                                                   + 8 * ks + 2 * tg];
                    mma_f16(d2[nf], a0, a1, a2, a3, bf.x, bf.y);
                }
            }

            // score = bd + sum_j sigmoid(D2+b2)*Wd ; reduce over tg
            float slo = 0.0f, shi = 0.0f;
            #pragma unroll
            for (int nf = 0; nf < 5; nf++) {
                int j0 = nf * 8 + 2 * tg;
                float blo = smf[SM_B2V + j0], bhi = smf[SM_B2V + j0 + 1];
                float wlo = smf[SM_WD + j0],  whi = smf[SM_WD + j0 + 1];
                slo += sigmoid_tanh(d2[nf][0] + blo) * wlo
                     + sigmoid_tanh(d2[nf][1] + bhi) * whi;
                shi += sigmoid_tanh(d2[nf][2] + blo) * wlo
                     + sigmoid_tanh(d2[nf][3] + bhi) * whi;
            }
            slo += __shfl_xor_sync(0xffffffffu, slo, 1);
            slo += __shfl_xor_sync(0xffffffffu, slo, 2);
            shi += __shfl_xor_sync(0xffffffffu, shi, 1);
            shi += __shfl_xor_sync(0xffffffffu, shi, 2);
            if (tg == 0) {
                int t0 = rbase + gr, t1 = rbase + gr + 8;
                if (t0 < L) smf[SM_SSC + t0] = slo + bdv;
                if (t1 < L) smf[SM_SSC + t1] = shi + bdv;
            }
        }
        __syncthreads();

        // ---- pooling from GLOBAL fp32 k (coalesced 256B per t) ----
        {
            int e = tid & 63, half = tid >> 6;
            const float* kp = kb + e;
            float acc = 0.0f;
            #pragma unroll 8
            for (int t = half; t < L; t += 2)
                acc += smf[SM_SSC + t] * kp[(size_t)t * EE];
            smf[SM_PART + tid] = acc;
        }
        __syncthreads();
        if (tid < EE)
            out[(size_t)b * EE + tid] = smf[SM_PART + tid] + smf[SM_PART + EE + tid];
        // loop-top __syncthreads protects K/SSC/PART reuse next iteration
    }
}

extern "C" void kernel_launch(void* const* d_in, const int* in_sizes, int n_in,
                              void* d_out, int out_size)
{
    const float* query = (const float*)d_in[0];
    const float* keys  = (const float*)d_in[1];
    const void*  klen  = d_in[2];
    const float* W1    = (const float*)d_in[3];
    const float* b1    = (const float*)d_in[4];
    const float* W2    = (const float*)d_in[5];
    const float* b2    = (const float*)d_in[6];
    const float* Wd    = (const float*)d_in[7];
    const float* bd    = (const float*)d_in[8];
    float* out = (float*)d_out;

    const int B = in_sizes[0] / EE;  // 4096

    static int configured = 0;
    if (!configured) {
        cudaFuncSetAttribute(din_mma_kernel,
                             cudaFuncAttributeMaxDynamicSharedMemorySize, SM_BYTES);
        configured = 1;
    }

    reset_ctr<<<1, 1>>>();
    prep_pack<<<20, 256>>>(W1, W2);
    din_mma_kernel<<<NCTA, 128, SM_BYTES>>>(query, keys, klen, b1, b2, Wd, bd,
                                            out, B);
}

// round 10
// speedup vs baseline: 1.3956x; 1.1271x over previous
#include <cuda_runtime.h>
#include <cstdint>

// DIN attention-seq-pooling, round 10: persistent CTAs, half-T K buffer.
// vs round 9 (92.3us): K staged in two passes of <=112 rows -> smem 54.7KB ->
// 39.4KB -> 5 CTAs/SM (was 4); NCTA 608->760; pooling uses 4 accumulators;
// counter reset folded into prep_pack. Tile math unchanged (fp16 m16n8k16,
// reg-resident h1, LDS.64 fragments, conflict-free strides).

#define TT 200
#define EE 64
#define HH1 80
#define HH2 40
#define KSTR 40      // all strides ≡ 8 mod 32 -> conflict-free LDS.64
#define B1STR 40
#define W2STR 40
#define NCTA 760
#define PASSROWS 112   // 7 tiles pass0, 6 tiles pass1

typedef unsigned long long ull;

__device__ float  g_W1sum[EE * HH1];       // W1a + W1c, [e*80+n]
__device__ float2 g_W1pair[HH1 * EE];      // {W1b-W1c, W1d}, [n*64+e]
__device__ unsigned g_W2Th[HH2 * W2STR];   // half2 image [n][phys k2]
__device__ int    g_ctr;                   // persistent work counter

// phys slot of logical half2-col c2 within its 8-col group
__host__ __device__ __forceinline__ int physcol(int c2) {
    int g = c2 >> 3, j = c2 & 7;
    return (g << 3) | ((j & 3) << 1) | (j >> 2);
}

__device__ __forceinline__ unsigned pack_h2(float lo, float hi) {
    unsigned r;
    asm("cvt.rn.f16x2.f32 %0, %1, %2;" : "=r"(r) : "f"(hi), "f"(lo));
    return r;
}
__device__ __forceinline__ float sigmoid_tanh(float x) {
    float t;
    asm("tanh.approx.f32 %0, %1;" : "=f"(t) : "f"(x * 0.5f));
    return fmaf(t, 0.5f, 0.5f);
}
__device__ __forceinline__ void mma_f16(float* d, unsigned a0, unsigned a1,
                                        unsigned a2, unsigned a3,
                                        unsigned b0, unsigned b1) {
    asm volatile(
        "mma.sync.aligned.m16n8k16.row.col.f32.f16.f16.f32 "
        "{%0,%1,%2,%3}, {%4,%5,%6,%7}, {%8,%9}, {%0,%1,%2,%3};"
        : "+f"(d[0]), "+f"(d[1]), "+f"(d[2]), "+f"(d[3])
        : "r"(a0), "r"(a1), "r"(a2), "r"(a3), "r"(b0), "r"(b1));
}

// ---------------- prep kernel (also resets work counter) ----------------
__global__ void prep_pack(const float* __restrict__ W1, const float* __restrict__ W2) {
    int i = blockIdx.x * 256 + threadIdx.x;
    if (i == 0) g_ctr = 0;
    if (i < EE * HH1) {                    // i = e*80+n, coalesced W1 reads
        int e = i / HH1, n = i - e * HH1;
        g_W1sum[i] = W1[i] + W1[2 * EE * HH1 + i];
        float2 p;
        p.x = W1[EE * HH1 + i] - W1[2 * EE * HH1 + i];
        p.y = W1[3 * EE * HH1 + i];
        g_W1pair[n * EE + e] = p;
    }
    if (i < HH2 * W2STR) {                 // 40 n x 40 logical half2-cols
        int n = i / W2STR, c2 = i - n * W2STR;
        float v0 = W2[(2 * c2) * HH2 + n];
        float v1 = W2[(2 * c2 + 1) * HH2 + n];
        g_W2Th[n * W2STR + physcol(c2)] = pack_h2(v0, v1);
    }
}

// ---------------- smem layout (32-bit word index) ----------------
#define SM_K    0                         // 112 x 40 = 4480
#define SM_B1   4480                      // 80 x 40 = 3200
#define SM_W2T  7680                      // 40 x 40 = 1600
#define SM_QW   9280                      // 80 f
#define SM_Q    9360                      // 64 f
#define SM_B2V  9424                      // 40 f
#define SM_WD   9464                      // 40 f
#define SM_SSC  9504                      // 208 f
#define SM_PART 9712                      // 128 f
#define SM_BIDX 9840                      // 1
#define SM_WORDS 9844
#define SM_BYTES (SM_WORDS * 4)           // 39376 -> 5 CTAs/SM (regs cap 102)

__global__ void __launch_bounds__(128, 5)
din_mma_kernel(const float* __restrict__ query,
               const float* __restrict__ keys,
               const void*  __restrict__ klen,
               const float* __restrict__ b1,
               const float* __restrict__ b2,
               const float* __restrict__ Wd,
               const float* __restrict__ bd,
               float* __restrict__ out,
               int B)
{
    extern __shared__ float smf[];
    unsigned* smu = (unsigned*)smf;
    int* smi = (int*)smf;
    const int tid  = threadIdx.x;
    const int wid  = tid >> 5;
    const int lane = tid & 31;
    const int gr   = lane >> 2;     // group row 0..7
    const int tg   = lane & 3;      // thread-in-group 0..3

    // ---- per-CTA one-time staging: W2T, b2, Wd ----
    if (tid < HH2) { smf[SM_B2V + tid] = b2[tid]; smf[SM_WD + tid] = Wd[tid]; }
    {
        const uint2* src = (const uint2*)g_W2Th;
        uint2* dst = (uint2*)&smu[SM_W2T];
        for (int i = tid; i < HH2 * W2STR / 2; i += 128) dst[i] = src[i];
    }
    const float bdv = bd[0];

    // ---- length dtype detection once (int64 vs silently-int32 jax) ----
    const long long* L64 = (const long long*)klen;
    const int*       L32 = (const int*)klen;
    const bool is64 = ((ull)L64[0] <= 0xFFFFFFFFull) && ((ull)L64[1] <= 0xFFFFFFFFull) &&
                      ((ull)L64[2] <= 0xFFFFFFFFull) && ((ull)L64[3] <= 0xFFFFFFFFull);

    // ---- persistent work loop ----
    while (true) {
        if (tid == 0) smi[SM_BIDX] = atomicAdd(&g_ctr, 1);
        __syncthreads();               // broadcast b; also fences prev batch
        const int b = smi[SM_BIDX];
        if (b >= B) break;

        int L = is64 ? (int)L64[b] : L32[b];
        if (L < 0) L = 0;
        if (L > TT) L = TT;
        if (L == 0) {
            if (tid < EE) out[(size_t)b * EE + tid] = 0.0f;
            continue;                  // uniform; loop-top sync re-converges
        }
        const int ntiles = (L + 15) >> 4;
        const int tiles_p0 = ntiles < 7 ? ntiles : 7;
        const int tiles_p1 = ntiles - tiles_p0;       // 0..6
        const float* kb = keys + (size_t)b * TT * EE;

        // ---- stage q + K pass 0 rows ----
        if (tid < EE) smf[SM_Q + tid] = query[(size_t)b * EE + tid];
        {
            const int nrows = tiles_p0 * 16;          // <= 112, always < TT
            for (int i = tid; i < nrows * 16; i += 128) {
                int r = i >> 4, c4 = i & 15;
                float4 v = *(const float4*)(kb + (size_t)r * EE + c4 * 4);
                smu[SM_K + r * KSTR + physcol(2 * c4)]     = pack_h2(v.x, v.y);
                smu[SM_K + r * KSTR + physcol(2 * c4 + 1)] = pack_h2(v.z, v.w);
            }
        }
        __syncthreads();

        // ---- qW = b1 + q @ W1sum ----
        if (tid < HH1) {
            float acc = b1[tid];
            #pragma unroll 8
            for (int e = 0; e < EE; e++)
                acc += smf[SM_Q + e] * g_W1sum[e * HH1 + tid];
            smf[SM_QW + tid] = acc;
        }
        // ---- B1eff half2 image: [n][phys e2],  bc + q_e * d ----
        for (int i = tid; i < HH1 * (EE / 2); i += 128) {
            int n = i >> 5, e2 = i & 31;
            float4 w = *(const float4*)&g_W1pair[n * EE + 2 * e2]; // {bc0,d0,bc1,d1}
            float q0 = smf[SM_Q + 2 * e2], q1 = smf[SM_Q + 2 * e2 + 1];
            smu[SM_B1 + n * B1STR + physcol(e2)] = pack_h2(fmaf(q0, w.y, w.x),
                                                           fmaf(q1, w.w, w.z));
        }
        __syncthreads();

        // ---- two passes over token tiles ----
        for (int p = 0; p < 2; p++) {
            const int tiles_p = p ? tiles_p1 : tiles_p0;
            if (tiles_p == 0) break;

            if (p == 1) {
                // restage K with pass-1 rows (global rows 112..)
                __syncthreads();       // all warps done reading pass-0 K
                const int nrows = tiles_p1 * 16;      // <= 96
                for (int i = tid; i < nrows * 16; i += 128) {
                    int r = i >> 4, c4 = i & 15;
                    int rg = PASSROWS + r;
                    float4 v = make_float4(0.f, 0.f, 0.f, 0.f);
                    if (rg < TT) v = *(const float4*)(kb + (size_t)rg * EE + c4 * 4);
                    smu[SM_K + r * KSTR + physcol(2 * c4)]     = pack_h2(v.x, v.y);
                    smu[SM_K + r * KSTR + physcol(2 * c4 + 1)] = pack_h2(v.z, v.w);
                }
                __syncthreads();
            }

            for (int lt = wid; lt < tiles_p; lt += 4) {
                const int rbase = (7 * p + lt) * 16;  // global token base
                const int r0 = lt * 16 + gr;          // K-buffer row
                const int r1 = r0 + 8;

                // MMA1: D1[16,80] = k @ B1eff  (4 ksteps of 16)
                float d1[10][4];
                #pragma unroll
                for (int nf = 0; nf < 10; nf++)
                    d1[nf][0] = d1[nf][1] = d1[nf][2] = d1[nf][3] = 0.0f;

                #pragma unroll
                for (int ks = 0; ks < 4; ks++) {
                    uint2 af0 = *(const uint2*)&smu[SM_K + r0 * KSTR + 8 * ks + 2 * tg];
                    uint2 af1 = *(const uint2*)&smu[SM_K + r1 * KSTR + 8 * ks + 2 * tg];
                    #pragma unroll
                    for (int nf = 0; nf < 10; nf++) {
                        uint2 bf = *(const uint2*)&smu[SM_B1 + (8 * nf + gr) * B1STR
                                                       + 8 * ks + 2 * tg];
                        mma_f16(d1[nf], af0.x, af1.x, af0.y, af1.y, bf.x, bf.y);
                    }
                }

                // h1 = sigmoid(D1 + qW) packed half2 in regs == MMA2 A-frags
                unsigned haA[10], haB[10];
                #pragma unroll
                for (int nf = 0; nf < 10; nf++) {
                    int j0 = nf * 8 + 2 * tg;
                    float qlo = smf[SM_QW + j0], qhi = smf[SM_QW + j0 + 1];
                    haA[nf] = pack_h2(sigmoid_tanh(d1[nf][0] + qlo),
                                      sigmoid_tanh(d1[nf][1] + qhi));
                    haB[nf] = pack_h2(sigmoid_tanh(d1[nf][2] + qlo),
                                      sigmoid_tanh(d1[nf][3] + qhi));
                }

                // MMA2: D2[16,40] = h1 @ W2T  (5 ksteps of 16)
                float d2[5][4];
                #pragma unroll
                for (int nf = 0; nf < 5; nf++)
                    d2[nf][0] = d2[nf][1] = d2[nf][2] = d2[nf][3] = 0.0f;

                #pragma unroll
                for (int ks = 0; ks < 5; ks++) {
                    unsigned a0 = haA[2 * ks];
                    unsigned a1 = haB[2 * ks];
                    unsigned a2 = haA[2 * ks + 1];
                    unsigned a3 = haB[2 * ks + 1];
                    #pragma unroll
                    for (int nf = 0; nf < 5; nf++) {
                        uint2 bf = *(const uint2*)&smu[SM_W2T + (8 * nf + gr) * W2STR
                                                       + 8 * ks + 2 * tg];
                        mma_f16(d2[nf], a0, a1, a2, a3, bf.x, bf.y);
                    }
                }

                // score = bd + sum_j sigmoid(D2+b2)*Wd ; reduce over tg
                float slo = 0.0f, shi = 0.0f;
                #pragma unroll
                for (int nf = 0; nf < 5; nf++) {
                    int j0 = nf * 8 + 2 * tg;
                    float blo = smf[SM_B2V + j0], bhi = smf[SM_B2V + j0 + 1];
                    float wlo = smf[SM_WD + j0],  whi = smf[SM_WD + j0 + 1];
                    slo += sigmoid_tanh(d2[nf][0] + blo) * wlo
                         + sigmoid_tanh(d2[nf][1] + bhi) * whi;
                    shi += sigmoid_tanh(d2[nf][2] + blo) * wlo
                         + sigmoid_tanh(d2[nf][3] + bhi) * whi;
                }
                slo += __shfl_xor_sync(0xffffffffu, slo, 1);
                slo += __shfl_xor_sync(0xffffffffu, slo, 2);
                shi += __shfl_xor_sync(0xffffffffu, shi, 1);
                shi += __shfl_xor_sync(0xffffffffu, shi, 2);
                if (tg == 0) {
                    int t0 = rbase + gr, t1 = rbase + gr + 8;
                    if (t0 < L) smf[SM_SSC + t0] = slo + bdv;
                    if (t1 < L) smf[SM_SSC + t1] = shi + bdv;
                }
            }
        }
        __syncthreads();

        // ---- pooling from GLOBAL fp32 k, 4 accumulators ----
        {
            int e = tid & 63, half = tid >> 6;
            const float* kp = kb + e;
            float a0 = 0.f, a1 = 0.f, a2 = 0.f, a3 = 0.f;
            int t = half;
            for (; t + 6 < L; t += 8) {
                a0 += smf[SM_SSC + t]     * kp[(size_t)t * EE];
                a1 += smf[SM_SSC + t + 2] * kp[(size_t)(t + 2) * EE];
                a2 += smf[SM_SSC + t + 4] * kp[(size_t)(t + 4) * EE];
                a3 += smf[SM_SSC + t + 6] * kp[(size_t)(t + 6) * EE];
            }
            for (; t < L; t += 2)
                a0 += smf[SM_SSC + t] * kp[(size_t)t * EE];
            smf[SM_PART + tid] = (a0 + a1) + (a2 + a3);
        }
        __syncthreads();
        if (tid < EE)
            out[(size_t)b * EE + tid] = smf[SM_PART + tid] + smf[SM_PART + EE + tid];
        // loop-top __syncthreads protects K/SSC/PART reuse next iteration
    }
}

extern "C" void kernel_launch(void* const* d_in, const int* in_sizes, int n_in,
                              void* d_out, int out_size)
{
    const float* query = (const float*)d_in[0];
    const float* keys  = (const float*)d_in[1];
    const void*  klen  = d_in[2];
    const float* W1    = (const float*)d_in[3];
    const float* b1    = (const float*)d_in[4];
    const float* W2    = (const float*)d_in[5];
    const float* b2    = (const float*)d_in[6];
    const float* Wd    = (const float*)d_in[7];
    const float* bd    = (const float*)d_in[8];
    float* out = (float*)d_out;

    const int B = in_sizes[0] / EE;  // 4096

    static int configured = 0;
    if (!configured) {
        cudaFuncSetAttribute(din_mma_kernel,
                             cudaFuncAttributeMaxDynamicSharedMemorySize, SM_BYTES);
        configured = 1;
    }

    prep_pack<<<20, 256>>>(W1, W2);
    din_mma_kernel<<<NCTA, 128, SM_BYTES>>>(query, keys, klen, b1, b2, Wd, bd,
                                            out, B);
}

// round 11
// speedup vs baseline: 1.4536x; 1.0415x over previous
#include <cuda_runtime.h>
#include <cstdint>

// DIN attention-seq-pooling, round 11: 6 CTAs/SM.
// vs round 10 (81.9us): K buffer 96 rows (<=3 passes) -> smem 36.8KB; MMA2
// interleaved with h1 conversion so d1 dies incrementally -> peak regs <= ~70,
// __launch_bounds__(128,6) (85-reg cap). NCTA 912. Tile math unchanged
// (fp16 m16n8k16, LDS.64 permuted fragments, persistent atomic queue).

#define TT 200
#define EE 64
#define HH1 80
#define HH2 40
#define KSTR 40      // all strides ≡ 8 mod 32 -> conflict-free LDS.64
#define B1STR 40
#define W2STR 40
#define NCTA 912
#define PTILES 6     // tiles per K pass (96 rows)

typedef unsigned long long ull;

__device__ float  g_W1sum[EE * HH1];       // W1a + W1c, [e*80+n]
__device__ float2 g_W1pair[HH1 * EE];      // {W1b-W1c, W1d}, [n*64+e]
__device__ unsigned g_W2Th[HH2 * W2STR];   // half2 image [n][phys k2]
__device__ int    g_ctr;                   // persistent work counter

// phys slot of logical half2-col c2 within its 8-col group
__host__ __device__ __forceinline__ int physcol(int c2) {
    int g = c2 >> 3, j = c2 & 7;
    return (g << 3) | ((j & 3) << 1) | (j >> 2);
}

__device__ __forceinline__ unsigned pack_h2(float lo, float hi) {
    unsigned r;
    asm("cvt.rn.f16x2.f32 %0, %1, %2;" : "=r"(r) : "f"(hi), "f"(lo));
    return r;
}
__device__ __forceinline__ float sigmoid_tanh(float x) {
    float t;
    asm("tanh.approx.f32 %0, %1;" : "=f"(t) : "f"(x * 0.5f));
    return fmaf(t, 0.5f, 0.5f);
}
__device__ __forceinline__ void mma_f16(float* d, unsigned a0, unsigned a1,
                                        unsigned a2, unsigned a3,
                                        unsigned b0, unsigned b1) {
    asm volatile(
        "mma.sync.aligned.m16n8k16.row.col.f32.f16.f16.f32 "
        "{%0,%1,%2,%3}, {%4,%5,%6,%7}, {%8,%9}, {%0,%1,%2,%3};"
        : "+f"(d[0]), "+f"(d[1]), "+f"(d[2]), "+f"(d[3])
        : "r"(a0), "r"(a1), "r"(a2), "r"(a3), "r"(b0), "r"(b1));
}

// ---------------- prep kernel (also resets work counter) ----------------
__global__ void prep_pack(const float* __restrict__ W1, const float* __restrict__ W2) {
    int i = blockIdx.x * 256 + threadIdx.x;
    if (i == 0) g_ctr = 0;
    if (i < EE * HH1) {                    // i = e*80+n, coalesced W1 reads
        int e = i / HH1, n = i - e * HH1;
        g_W1sum[i] = W1[i] + W1[2 * EE * HH1 + i];
        float2 p;
        p.x = W1[EE * HH1 + i] - W1[2 * EE * HH1 + i];
        p.y = W1[3 * EE * HH1 + i];
        g_W1pair[n * EE + e] = p;
    }
    if (i < HH2 * W2STR) {                 // 40 n x 40 logical half2-cols
        int n = i / W2STR, c2 = i - n * W2STR;
        float v0 = W2[(2 * c2) * HH2 + n];
        float v1 = W2[(2 * c2 + 1) * HH2 + n];
        g_W2Th[n * W2STR + physcol(c2)] = pack_h2(v0, v1);
    }
}

// ---------------- smem layout (32-bit word index) ----------------
#define SM_K    0                         // 96 x 40 = 3840
#define SM_B1   3840                      // 80 x 40 = 3200
#define SM_W2T  7040                      // 40 x 40 = 1600
#define SM_QW   8640                      // 80 f
#define SM_Q    8720                      // 64 f
#define SM_B2V  8784                      // 40 f
#define SM_WD   8824                      // 40 f
#define SM_SSC  8864                      // 208 f
#define SM_PART 9072                      // 128 f
#define SM_BIDX 9200                      // 1
#define SM_WORDS 9204
#define SM_BYTES (SM_WORDS * 4)           // 36816 -> 6 CTAs/SM (regs <= 85)

__global__ void __launch_bounds__(128, 6)
din_mma_kernel(const float* __restrict__ query,
               const float* __restrict__ keys,
               const void*  __restrict__ klen,
               const float* __restrict__ b1,
               const float* __restrict__ b2,
               const float* __restrict__ Wd,
               const float* __restrict__ bd,
               float* __restrict__ out,
               int B)
{
    extern __shared__ float smf[];
    unsigned* smu = (unsigned*)smf;
    int* smi = (int*)smf;
    const int tid  = threadIdx.x;
    const int wid  = tid >> 5;
    const int lane = tid & 31;
    const int gr   = lane >> 2;     // group row 0..7
    const int tg   = lane & 3;      // thread-in-group 0..3

    // ---- per-CTA one-time staging: W2T, b2, Wd ----
    if (tid < HH2) { smf[SM_B2V + tid] = b2[tid]; smf[SM_WD + tid] = Wd[tid]; }
    {
        const uint2* src = (const uint2*)g_W2Th;
        uint2* dst = (uint2*)&smu[SM_W2T];
        for (int i = tid; i < HH2 * W2STR / 2; i += 128) dst[i] = src[i];
    }
    const float bdv = bd[0];

    // ---- length dtype detection once (int64 vs silently-int32 jax) ----
    const long long* L64 = (const long long*)klen;
    const int*       L32 = (const int*)klen;
    const bool is64 = ((ull)L64[0] <= 0xFFFFFFFFull) && ((ull)L64[1] <= 0xFFFFFFFFull) &&
                      ((ull)L64[2] <= 0xFFFFFFFFull) && ((ull)L64[3] <= 0xFFFFFFFFull);

    // ---- persistent work loop ----
    while (true) {
        if (tid == 0) smi[SM_BIDX] = atomicAdd(&g_ctr, 1);
        __syncthreads();               // broadcast b; also fences prev batch
        const int b = smi[SM_BIDX];
        if (b >= B) break;

        int L = is64 ? (int)L64[b] : L32[b];
        if (L < 0) L = 0;
        if (L > TT) L = TT;
        if (L == 0) {
            if (tid < EE) out[(size_t)b * EE + tid] = 0.0f;
            continue;                  // uniform; loop-top sync re-converges
        }
        const int ntiles = (L + 15) >> 4;
        const float* kb = keys + (size_t)b * TT * EE;

        // ---- stage q + K pass 0 (rows 0..95, always in range) ----
        if (tid < EE) smf[SM_Q + tid] = query[(size_t)b * EE + tid];
        {
            const int tiles0 = ntiles < PTILES ? ntiles : PTILES;
            for (int i = tid; i < tiles0 * 256; i += 128) {
                int r = i >> 4, c4 = i & 15;
                float4 v = *(const float4*)(kb + (size_t)r * EE + c4 * 4);
                smu[SM_K + r * KSTR + physcol(2 * c4)]     = pack_h2(v.x, v.y);
                smu[SM_K + r * KSTR + physcol(2 * c4 + 1)] = pack_h2(v.z, v.w);
            }
        }
        __syncthreads();

        // ---- qW = b1 + q @ W1sum ----
        if (tid < HH1) {
            float acc = b1[tid];
            #pragma unroll 8
            for (int e = 0; e < EE; e++)
                acc += smf[SM_Q + e] * g_W1sum[e * HH1 + tid];
            smf[SM_QW + tid] = acc;
        }
        // ---- B1eff half2 image: [n][phys e2],  bc + q_e * d ----
        for (int i = tid; i < HH1 * (EE / 2); i += 128) {
            int n = i >> 5, e2 = i & 31;
            float4 w = *(const float4*)&g_W1pair[n * EE + 2 * e2]; // {bc0,d0,bc1,d1}
            float q0 = smf[SM_Q + 2 * e2], q1 = smf[SM_Q + 2 * e2 + 1];
            smu[SM_B1 + n * B1STR + physcol(e2)] = pack_h2(fmaf(q0, w.y, w.x),
                                                           fmaf(q1, w.w, w.z));
        }
        __syncthreads();

        // ---- passes of up to 6 tiles over the 96-row K buffer ----
        for (int tb = 0; ; ) {
            const int tiles_p = (ntiles - tb) < PTILES ? (ntiles - tb) : PTILES;

            for (int lt = wid; lt < tiles_p; lt += 4) {
                const int rbase = (tb + lt) * 16;     // global token base
                const int r0 = lt * 16 + gr;          // K-buffer row
                const int r1 = r0 + 8;

                // MMA1: D1[16,80] = k @ B1eff  (4 ksteps of 16)
                float d1[10][4];
                #pragma unroll
                for (int nf = 0; nf < 10; nf++)
                    d1[nf][0] = d1[nf][1] = d1[nf][2] = d1[nf][3] = 0.0f;

                #pragma unroll
                for (int ks = 0; ks < 4; ks++) {
                    uint2 af0 = *(const uint2*)&smu[SM_K + r0 * KSTR + 8 * ks + 2 * tg];
                    uint2 af1 = *(const uint2*)&smu[SM_K + r1 * KSTR + 8 * ks + 2 * tg];
                    #pragma unroll
                    for (int nf = 0; nf < 10; nf++) {
                        uint2 bf = *(const uint2*)&smu[SM_B1 + (8 * nf + gr) * B1STR
                                                       + 8 * ks + 2 * tg];
                        mma_f16(d1[nf], af0.x, af1.x, af0.y, af1.y, bf.x, bf.y);
                    }
                }

                // MMA2 interleaved with h1 conversion: at kstep ks consume
                // d1 fragments nf=2ks,2ks+1 (d1 dies incrementally).
                float d2[5][4];
                #pragma unroll
                for (int nf = 0; nf < 5; nf++)
                    d2[nf][0] = d2[nf][1] = d2[nf][2] = d2[nf][3] = 0.0f;

                #pragma unroll
                for (int ks = 0; ks < 5; ks++) {
                    const int nfA = 2 * ks, nfB = 2 * ks + 1;
                    int jA = nfA * 8 + 2 * tg, jB = nfB * 8 + 2 * tg;
                    float qloA = smf[SM_QW + jA], qhiA = smf[SM_QW + jA + 1];
                    float qloB = smf[SM_QW + jB], qhiB = smf[SM_QW + jB + 1];
                    unsigned a0 = pack_h2(sigmoid_tanh(d1[nfA][0] + qloA),
                                          sigmoid_tanh(d1[nfA][1] + qhiA));
                    unsigned a1 = pack_h2(sigmoid_tanh(d1[nfA][2] + qloA),
                                          sigmoid_tanh(d1[nfA][3] + qhiA));
                    unsigned a2 = pack_h2(sigmoid_tanh(d1[nfB][0] + qloB),
                                          sigmoid_tanh(d1[nfB][1] + qhiB));
                    unsigned a3 = pack_h2(sigmoid_tanh(d1[nfB][2] + qloB),
                                          sigmoid_tanh(d1[nfB][3] + qhiB));
                    #pragma unroll
                    for (int nf = 0; nf < 5; nf++) {
                        uint2 bf = *(const uint2*)&smu[SM_W2T + (8 * nf + gr) * W2STR
                                                       + 8 * ks + 2 * tg];
                        mma_f16(d2[nf], a0, a1, a2, a3, bf.x, bf.y);
                    }
                }

                // score = bd + sum_j sigmoid(D2+b2)*Wd ; reduce over tg
                float slo = 0.0f, shi = 0.0f;
                #pragma unroll
                for (int nf = 0; nf < 5; nf++) {
                    int j0 = nf * 8 + 2 * tg;
                    float blo = smf[SM_B2V + j0], bhi = smf[SM_B2V + j0 + 1];
                    float wlo = smf[SM_WD + j0],  whi = smf[SM_WD + j0 + 1];
                    slo += sigmoid_tanh(d2[nf][0] + blo) * wlo
                         + sigmoid_tanh(d2[nf][1] + bhi) * whi;
                    shi += sigmoid_tanh(d2[nf][2] + blo) * wlo
                         + sigmoid_tanh(d2[nf][3] + bhi) * whi;
                }
                slo += __shfl_xor_sync(0xffffffffu, slo, 1);
                slo += __shfl_xor_sync(0xffffffffu, slo, 2);
                shi += __shfl_xor_sync(0xffffffffu, shi, 1);
                shi += __shfl_xor_sync(0xffffffffu, shi, 2);
                if (tg == 0) {
                    int t0 = rbase + gr, t1 = rbase + gr + 8;
                    if (t0 < L) smf[SM_SSC + t0] = slo + bdv;
                    if (t1 < L) smf[SM_SSC + t1] = shi + bdv;
                }
            }

            tb += PTILES;
            if (tb >= ntiles) break;

            // restage K with this pass's rows
            __syncthreads();           // all warps done reading prev K
            {
                const int tiles_p2 = (ntiles - tb) < PTILES ? (ntiles - tb) : PTILES;
                for (int i = tid; i < tiles_p2 * 256; i += 128) {
                    int r = i >> 4, c4 = i & 15;
                    int rg = tb * 16 + r;
                    float4 v = make_float4(0.f, 0.f, 0.f, 0.f);
                    if (rg < TT) v = *(const float4*)(kb + (size_t)rg * EE + c4 * 4);
                    smu[SM_K + r * KSTR + physcol(2 * c4)]     = pack_h2(v.x, v.y);
                    smu[SM_K + r * KSTR + physcol(2 * c4 + 1)] = pack_h2(v.z, v.w);
                }
            }
            __syncthreads();
        }
        __syncthreads();

        // ---- pooling from GLOBAL fp32 k, 4 accumulators ----
        {
            int e = tid & 63, half = tid >> 6;
            const float* kp = kb + e;
            float a0 = 0.f, a1 = 0.f, a2 = 0.f, a3 = 0.f;
            int t = half;
            for (; t + 6 < L; t += 8) {
                a0 += smf[SM_SSC + t]     * kp[(size_t)t * EE];
                a1 += smf[SM_SSC + t + 2] * kp[(size_t)(t + 2) * EE];
                a2 += smf[SM_SSC + t + 4] * kp[(size_t)(t + 4) * EE];
                a3 += smf[SM_SSC + t + 6] * kp[(size_t)(t + 6) * EE];
            }
            for (; t < L; t += 2)
                a0 += smf[SM_SSC + t] * kp[(size_t)t * EE];
            smf[SM_PART + tid] = (a0 + a1) + (a2 + a3);
        }
        __syncthreads();
        if (tid < EE)
            out[(size_t)b * EE + tid] = smf[SM_PART + tid] + smf[SM_PART + EE + tid];
        // loop-top __syncthreads protects K/SSC/PART reuse next iteration
    }
}

extern "C" void kernel_launch(void* const* d_in, const int* in_sizes, int n_in,
                              void* d_out, int out_size)
{
    const float* query = (const float*)d_in[0];
    const float* keys  = (const float*)d_in[1];
    const void*  klen  = d_in[2];
    const float* W1    = (const float*)d_in[3];
    const float* b1    = (const float*)d_in[4];
    const float* W2    = (const float*)d_in[5];
    const float* b2    = (const float*)d_in[6];
    const float* Wd    = (const float*)d_in[7];
    const float* bd    = (const float*)d_in[8];
    float* out = (float*)d_out;

    const int B = in_sizes[0] / EE;  // 4096

    static int configured = 0;
    if (!configured) {
        cudaFuncSetAttribute(din_mma_kernel,
                             cudaFuncAttributeMaxDynamicSharedMemorySize, SM_BYTES);
        configured = 1;
    }

    prep_pack<<<20, 256>>>(W1, W2);
    din_mma_kernel<<<NCTA, 128, SM_BYTES>>>(query, keys, klen, b1, b2, Wd, bd,
                                            out, B);
}